// round 14
// baseline (speedup 1.0000x reference)
#include <cuda_runtime.h>
#include <cuda_bf16.h>
#include <cstdint>
#include <cstddef>

#define QLEN   1024
#define BATCH  8
#define DMODEL 512
#define NHEAD  8
#define DHEAD  64
#define DINNER 2048
#define ELEN   1024
#define ATT_SCALE 0.125f
#define ROWS (QLEN * BATCH)   /* 8192 */

// ===================== warp MMA helpers =====================================
__device__ __forceinline__ uint32_t smem_u32(const void* p) {
    uint32_t a;
    asm("{ .reg .u64 t; cvta.to.shared.u64 t, %1; cvt.u32.u64 %0, t; }"
        : "=r"(a) : "l"(p));
    return a;
}

__device__ __forceinline__ void ldsm4(uint32_t* r, uint32_t addr) {
    asm volatile("ldmatrix.sync.aligned.m8n8.x4.shared.b16 {%0,%1,%2,%3}, [%4];"
                 : "=r"(r[0]), "=r"(r[1]), "=r"(r[2]), "=r"(r[3]) : "r"(addr));
}

__device__ __forceinline__ void mma16816(float* d, const uint32_t* a, const uint32_t* b) {
    asm volatile(
        "mma.sync.aligned.m16n8k16.row.col.f32.bf16.bf16.f32 "
        "{%0,%1,%2,%3}, {%4,%5,%6,%7}, {%8,%9}, {%0,%1,%2,%3};"
        : "+f"(d[0]), "+f"(d[1]), "+f"(d[2]), "+f"(d[3])
        : "r"(a[0]), "r"(a[1]), "r"(a[2]), "r"(a[3]), "r"(b[0]), "r"(b[1]));
}

__device__ __forceinline__ void cpa16(uint32_t dst, const void* src) {
    asm volatile("cp.async.cg.shared.global [%0], [%1], 16;" :: "r"(dst), "l"(src));
}

// predicated: src_size 0 zero-fills the 16B destination
__device__ __forceinline__ void cpa16p(uint32_t dst, const void* src, int ok) {
    asm volatile("cp.async.cg.shared.global [%0], [%1], 16, %2;"
                 :: "r"(dst), "l"(src), "r"(ok ? 16 : 0));
}

__device__ __forceinline__ void barp(int id) {
    asm volatile("bar.sync %0, %1;" :: "r"(id), "r"(64) : "memory");
}

// 128-thread (warp-quad) barrier
__device__ __forceinline__ void barq(int id) {
    asm volatile("bar.sync %0, %1;" :: "r"(id), "r"(128) : "memory");
}

// nt=4 variant (32-col B), 144B stride
__device__ __forceinline__ void wgemm3_nt4(uint32_t Ah, uint32_t Al,
                                           uint32_t Bh, uint32_t Bl,
                                           uint32_t a_off, uint32_t b_off,
                                           float acc[4][4])
{
    #pragma unroll
    for (int ks = 0; ks < 4; ks++) {
        const uint32_t ra = (uint32_t)(ks << 5);
        uint32_t ah[4], al[4];
        ldsm4(ah, Ah + ra + a_off);
        ldsm4(al, Al + ra + a_off);
        #pragma unroll
        for (int np = 0; np < 2; np++) {
            uint32_t bh[4], bl[4];
            const uint32_t rb = (uint32_t)(np * 16 * 144 + (ks << 5));
            ldsm4(bh, Bh + rb + b_off);
            ldsm4(bl, Bl + rb + b_off);
            #pragma unroll
            for (int hf = 0; hf < 2; hf++) {
                float* d = acc[(np << 1) + hf];
                mma16816(d, ah, bh + (hf << 1));
                mma16816(d, ah, bl + (hf << 1));
                mma16816(d, al, bh + (hf << 1));
            }
        }
    }
}

// nt=2 variant (16-col B), 144B stride
__device__ __forceinline__ void wgemm3_nt2(uint32_t Ah, uint32_t Al,
                                           uint32_t Bh, uint32_t Bl,
                                           uint32_t a_off, uint32_t b_off,
                                           float acc[2][4])
{
    #pragma unroll
    for (int ks = 0; ks < 4; ks++) {
        const uint32_t ra = (uint32_t)(ks << 5);
        uint32_t ah[4], al[4];
        ldsm4(ah, Ah + ra + a_off);
        ldsm4(al, Al + ra + a_off);
        uint32_t bh[4], bl[4];
        ldsm4(bh, Bh + ra + b_off);
        ldsm4(bl, Bl + ra + b_off);
        #pragma unroll
        for (int hf = 0; hf < 2; hf++) {
            float* d = acc[hf];
            mma16816(d, ah, bh + (hf << 1));
            mma16816(d, ah, bl + (hf << 1));
            mma16816(d, al, bh + (hf << 1));
        }
    }
}

__device__ __forceinline__ void split_store4(char* hi, char* lo, float4 v) {
    const __nv_bfloat16 h0 = __float2bfloat16(v.x), h1 = __float2bfloat16(v.y);
    const __nv_bfloat16 h2 = __float2bfloat16(v.z), h3 = __float2bfloat16(v.w);
    *(__nv_bfloat162*)(hi)     = __halves2bfloat162(h0, h1);
    *(__nv_bfloat162*)(hi + 4) = __halves2bfloat162(h2, h3);
    *(__nv_bfloat162*)(lo)     = __halves2bfloat162(
        __float2bfloat16(v.x - __bfloat162float(h0)),
        __float2bfloat16(v.y - __bfloat162float(h1)));
    *(__nv_bfloat162*)(lo + 4) = __halves2bfloat162(
        __float2bfloat16(v.z - __bfloat162float(h2)),
        __float2bfloat16(v.w - __bfloat162float(h3)));
}

// ===================== scratch ==============================================
__device__ float g_out1[ROWS * DMODEL];
__device__ float g_h2  [ROWS * DMODEL];
__device__ float g_out2[ROWS * DMODEL];
__device__ float g_qbias[3 * DMODEL];
__device__ float g_cc  [NHEAD * 1152];        // zero-init pad beyond 1024

__device__ __nv_bfloat16 g_hh[ROWS * DMODEL],    g_hl[ROWS * DMODEL];
__device__ __nv_bfloat16 g_headsh[ROWS * 1536],  g_headsl[ROWS * 1536];
__device__ __nv_bfloat16 g_rh[QLEN * DMODEL],    g_rl[QLEN * DMODEL];
__device__ __nv_bfloat16 g_rkh[QLEN * DMODEL],   g_rkl[QLEN * DMODEL];
__device__ __nv_bfloat16 g_vth[64 * 64 * QLEN],  g_vtl[64 * 64 * QLEN];
__device__ __nv_bfloat16 g_vech[ROWS * DMODEL],  g_vecl[ROWS * DMODEL];
__device__ __nv_bfloat16 g_h2h[ROWS * DMODEL],   g_h2l[ROWS * DMODEL];
__device__ __nv_bfloat16 g_q2h[ROWS * DMODEL],   g_q2l[ROWS * DMODEL];
__device__ __nv_bfloat16 g_eh[ROWS * DMODEL],    g_el[ROWS * DMODEL];
__device__ __nv_bfloat16 g_kvh[ROWS * 1024],     g_kvl[ROWS * 1024];
__device__ __nv_bfloat16 g_vt2h[64 * 64 * ELEN], g_vt2l[64 * 64 * ELEN];
__device__ __nv_bfloat16 g_vec2h[ROWS * DMODEL], g_vec2l[ROWS * DMODEL];
__device__ __nv_bfloat16 g_th[ROWS * DINNER],    g_tl[ROWS * DINNER];

#define WT_QKV 0
#define WT_RW  786432
#define WT_OW  1048576
#define WT_QW  1310720
#define WT_KVW 1572864
#define WT_O2W 2097152
#define WT_FF1 2359296
#define WT_FF2 3407872
#define WT_TOTAL 4456448
__device__ __nv_bfloat16 g_wthi[WT_TOTAL];
__device__ __nv_bfloat16 g_wtlo[WT_TOTAL];

// ===================== small prep kernels ===================================
__global__ __launch_bounds__(256) void split_k(const float* __restrict__ x,
                                               __nv_bfloat16* __restrict__ hi,
                                               __nv_bfloat16* __restrict__ lo, int n4)
{
    const int i = blockIdx.x * 256 + threadIdx.x;
    if (i >= n4) return;
    const float4 v = reinterpret_cast<const float4*>(x)[i];
    split_store4((char*)(hi + (size_t)i * 4), (char*)(lo + (size_t)i * 4), v);
}

// all 8 weight transposes+splits in one launch (linear block-range dispatch)
__global__ __launch_bounds__(256) void tsplit_all(
    const float* __restrict__ qkv, const float* __restrict__ rw,
    const float* __restrict__ ow,  const float* __restrict__ qw,
    const float* __restrict__ kvw, const float* __restrict__ o2w,
    const float* __restrict__ ff1, const float* __restrict__ ff2,
    __nv_bfloat16* __restrict__ hi, __nv_bfloat16* __restrict__ lo)
{
    int bid = blockIdx.x;
    const float* W; int K, N, gx; size_t off;
    if (bid < 768)                      { W = qkv; K = 512;  N = 1536; gx = 48; off = WT_QKV; }
    else if ((bid -= 768)  < 256)       { W = rw;  K = 512;  N = 512;  gx = 16; off = WT_RW;  }
    else if ((bid -= 256)  < 256)       { W = ow;  K = 512;  N = 512;  gx = 16; off = WT_OW;  }
    else if ((bid -= 256)  < 256)       { W = qw;  K = 512;  N = 512;  gx = 16; off = WT_QW;  }
    else if ((bid -= 256)  < 512)       { W = kvw; K = 512;  N = 1024; gx = 32; off = WT_KVW; }
    else if ((bid -= 512)  < 256)       { W = o2w; K = 512;  N = 512;  gx = 16; off = WT_O2W; }
    else if ((bid -= 256)  < 1024)      { W = ff1; K = 512;  N = 2048; gx = 64; off = WT_FF1; }
    else { bid -= 1024;                   W = ff2; K = 2048; N = 512;  gx = 16; off = WT_FF2; }

    __shared__ float t[32][33];
    const int n0 = (bid % gx) << 5, k0 = (bid / gx) << 5;
    const int x = threadIdx.x & 31, y = threadIdx.x >> 5;
    #pragma unroll
    for (int i = 0; i < 32; i += 8)
        t[y + i][x] = W[(size_t)(k0 + y + i) * N + n0 + x];
    __syncthreads();
    #pragma unroll
    for (int i = 0; i < 32; i += 8) {
        const float v = t[x][y + i];
        const size_t o = off + (size_t)(n0 + y + i) * K + k0 + x;
        const __nv_bfloat16 h = __float2bfloat16(v);
        hi[o] = h;
        lo[o] = __float2bfloat16(v - __bfloat162float(h));
    }
}

__global__ void qbias_k(const float* __restrict__ rwb, float* __restrict__ qb) {
    const int i = blockIdx.x * 256 + threadIdx.x;
    if (i < 1536) qb[i] = (i < 512) ? rwb[i] : 0.0f;
}

// c[n][u] = sum_d (rrb-rwb)[n][d] * rk[u][n*64+d]
__global__ __launch_bounds__(256) void c_k(const __nv_bfloat16* __restrict__ rkh,
                                           const __nv_bfloat16* __restrict__ rkl,
                                           const float* __restrict__ rwb,
                                           const float* __restrict__ rrb,
                                           float* __restrict__ cc)
{
    const int u = blockIdx.x;
    const int n = threadIdx.x >> 5, lane = threadIdx.x & 31;
    float s = 0.0f;
    #pragma unroll
    for (int k = 0; k < 2; k++) {
        const int d = lane + k * 32;
        const size_t g = (size_t)u * 512 + n * 64 + d;
        const float rv = __bfloat162float(rkh[g]) + __bfloat162float(rkl[g]);
        s += (rrb[n * 64 + d] - rwb[n * 64 + d]) * rv;
    }
    #pragma unroll
    for (int o = 16; o; o >>= 1) s += __shfl_xor_sync(0xffffffffu, s, o);
    if (lane == 0) cc[n * 1152 + u] = s;
}

// transpose V-part: src[(i*8+b)*stride + off + n*64 + d] -> dst[((b*8+n)*64+d)*1024 + i]
__global__ __launch_bounds__(256) void vtrans_k(const __nv_bfloat16* __restrict__ sh,
                                                const __nv_bfloat16* __restrict__ sl,
                                                __nv_bfloat16* __restrict__ dh,
                                                __nv_bfloat16* __restrict__ dl,
                                                int srcStride, int srcOff)
{
    __shared__ __nv_bfloat16 th[32][72], tl[32][72];
    const int i0 = blockIdx.x << 5;
    const int b = blockIdx.y >> 3, n = blockIdx.y & 7;
    const int t = threadIdx.x;
    {
        const int il = t >> 3, dj = (t & 7) << 3;
        const size_t g = ((size_t)(i0 + il) * 8 + b) * srcStride + srcOff + n * 64 + dj;
        *(uint4*)&th[il][dj] = *(const uint4*)(sh + g);
        *(uint4*)&tl[il][dj] = *(const uint4*)(sl + g);
    }
    __syncthreads();
    {
        const int dr = t >> 2, ij = (t & 3) << 3;
        __nv_bfloat16 oh[8], ol[8];
        #pragma unroll
        for (int k = 0; k < 8; k++) { oh[k] = th[ij + k][dr]; ol[k] = tl[ij + k][dr]; }
        const size_t g = ((size_t)(b * 8 + n) * 64 + dr) * 1024 + i0 + ij;
        *(uint4*)(dh + g) = *(uint4*)oh;
        *(uint4*)(dl + g) = *(uint4*)ol;
    }
}

// ===================== pipelined HMMA GEMM ==================================
// K-chunk 32, 2-stage cp.async double buffer. Tiles [128][40] bf16, 80B stride.
#define GP_STAGE 40960
#define GP_SMEM  81920

template <bool GELU, bool SPLIT>
__global__ __launch_bounds__(256, 2) void gemm_hmma(const __nv_bfloat16* __restrict__ Ahi,
                                                    const __nv_bfloat16* __restrict__ Alo,
                                                    const __nv_bfloat16* __restrict__ Bhi,
                                                    const __nv_bfloat16* __restrict__ Blo,
                                                    const float* __restrict__ bias,
                                                    const float* __restrict__ res,
                                                    float* __restrict__ C,
                                                    __nv_bfloat16* __restrict__ Ch,
                                                    __nv_bfloat16* __restrict__ Cl,
                                                    int M, int N, int K)
{
    extern __shared__ char smem[];
    const uint32_t sb = smem_u32(smem);
    const int tid = threadIdx.x;
    const int lane = tid & 31, wid = tid >> 5;
    const int m0 = blockIdx.y << 7, n0 = blockIdx.x << 7;
    const int wm = (wid & 3) << 5;
    const int wn = (wid >> 2) << 6;
    (void)M;

    float acc[2][8][4];
    #pragma unroll
    for (int mt = 0; mt < 2; mt++)
        #pragma unroll
        for (int nt = 0; nt < 8; nt++)
            #pragma unroll
            for (int e = 0; e < 4; e++) acc[mt][nt][e] = 0.0f;

    const int lr = lane & 7, lg = lane >> 3;
    const uint32_t a_off = (uint32_t)(((lg & 1) << 3) + lr) * 80u + (uint32_t)((lg >> 1) << 4);
    const uint32_t b_off = (uint32_t)(((lg >> 1) << 3) + lr) * 80u + (uint32_t)((lg & 1) << 4);

    const int nch = K >> 5;

    auto load_chunk = [&](int c, int s) {
        const int k0 = c << 5;
        const uint32_t sbase = sb + s * GP_STAGE;
        #pragma unroll
        for (int i = tid; i < 2048; i += 256) {
            const int tile = i >> 9;
            const int idx = i & 511;
            const int row = idx >> 2, kc = (idx & 3) << 3;
            const uint32_t dst = sbase + tile * 10240 + row * 80 + (idx & 3) * 16;
            const __nv_bfloat16* src;
            if (tile == 0)      src = Ahi + (size_t)(m0 + row) * K + k0 + kc;
            else if (tile == 1) src = Alo + (size_t)(m0 + row) * K + k0 + kc;
            else if (tile == 2) src = Bhi + (size_t)(n0 + row) * K + k0 + kc;
            else                src = Blo + (size_t)(n0 + row) * K + k0 + kc;
            cpa16(dst, src);
        }
        asm volatile("cp.async.commit_group;" ::: "memory");
    };

    load_chunk(0, 0);
    load_chunk(1, 1);

    for (int c = 0; c < nch; c++) {
        if (c + 1 < nch) asm volatile("cp.async.wait_group 1;" ::: "memory");
        else             asm volatile("cp.async.wait_group 0;" ::: "memory");
        __syncthreads();

        const uint32_t sbase = sb + (c & 1) * GP_STAGE;
        #pragma unroll
        for (int ks = 0; ks < 2; ks++) {
            const uint32_t kk2 = (uint32_t)(ks << 5);
            uint32_t ah[2][4], al[2][4];
            #pragma unroll
            for (int mt = 0; mt < 2; mt++) {
                const uint32_t ra = (uint32_t)((wm + (mt << 4)) * 80) + kk2 + a_off;
                ldsm4(ah[mt], sbase + ra);
                ldsm4(al[mt], sbase + 10240 + ra);
            }
            #pragma unroll
            for (int np = 0; np < 4; np++) {
                uint32_t bh[4], bl[4];
                const uint32_t rb = (uint32_t)((wn + (np << 4)) * 80) + kk2 + b_off;
                ldsm4(bh, sbase + 20480 + rb);
                ldsm4(bl, sbase + 30720 + rb);
                #pragma unroll
                for (int mt = 0; mt < 2; mt++) {
                    #pragma unroll
                    for (int hf = 0; hf < 2; hf++) {
                        float* d = acc[mt][(np << 1) + hf];
                        mma16816(d, ah[mt], bh + (hf << 1));
                        mma16816(d, ah[mt], bl + (hf << 1));
                        mma16816(d, al[mt], bh + (hf << 1));
                    }
                }
            }
        }
        __syncthreads();
        if (c + 2 < nch) load_chunk(c + 2, c & 1);
    }

    const int er = lane >> 2, ec = (lane & 3) << 1;
    #pragma unroll
    for (int mt = 0; mt < 2; mt++) {
        #pragma unroll
        for (int half = 0; half < 2; half++) {
            const int gr = m0 + wm + (mt << 4) + er + (half << 3);
            #pragma unroll
            for (int nt = 0; nt < 8; nt++) {
                const int gc = n0 + wn + (nt << 3) + ec;
                float v0 = acc[mt][nt][(half << 1) + 0];
                float v1 = acc[mt][nt][(half << 1) + 1];
                if (bias) { v0 += bias[gc]; v1 += bias[gc + 1]; }
                if (GELU) {
                    v0 = 0.5f * v0 * (1.0f + erff(v0 * 0.70710678118654752f));
                    v1 = 0.5f * v1 * (1.0f + erff(v1 * 0.70710678118654752f));
                }
                if (SPLIT) {
                    const __nv_bfloat16 h0 = __float2bfloat16(v0), h1 = __float2bfloat16(v1);
                    *(__nv_bfloat162*)(Ch + (size_t)gr * N + gc) = __halves2bfloat162(h0, h1);
                    *(__nv_bfloat162*)(Cl + (size_t)gr * N + gc) = __halves2bfloat162(
                        __float2bfloat16(v0 - __bfloat162float(h0)),
                        __float2bfloat16(v1 - __bfloat162float(h1)));
                } else {
                    if (res) {
                        const float2 rr = *reinterpret_cast<const float2*>(&res[(size_t)gr * N + gc]);
                        v0 += rr.x; v1 += rr.y;
                    }
                    *reinterpret_cast<float2*>(&C[(size_t)gr * N + gc]) = make_float2(v0, v1);
                }
            }
        }
    }
}

// ===================== LayerNorm ============================================
template <bool F32O, bool SPL>
__global__ __launch_bounds__(128) void ln_k(const float* __restrict__ x,
                                            const float* __restrict__ g,
                                            const float* __restrict__ b,
                                            float* __restrict__ yf,
                                            __nv_bfloat16* __restrict__ yh,
                                            __nv_bfloat16* __restrict__ yl)
{
    const int row = blockIdx.x;
    const int t = threadIdx.x;
    const float4 v = reinterpret_cast<const float4*>(x + (size_t)row * DMODEL)[t];
    float s  = v.x + v.y + v.z + v.w;
    float sq = v.x*v.x + v.y*v.y + v.z*v.z + v.w*v.w;
    #pragma unroll
    for (int o = 16; o; o >>= 1) {
        s  += __shfl_xor_sync(0xffffffffu, s,  o);
        sq += __shfl_xor_sync(0xffffffffu, sq, o);
    }
    __shared__ float ss[4], sqq[4];
    const int w = t >> 5, lane = t & 31;
    if (lane == 0) { ss[w] = s; sqq[w] = sq; }
    __syncthreads();
    s  = ss[0]  + ss[1]  + ss[2]  + ss[3];
    sq = sqq[0] + sqq[1] + sqq[2] + sqq[3];
    const float mean = s * (1.0f / DMODEL);
    const float var  = sq * (1.0f / DMODEL) - mean * mean;
    const float rstd = rsqrtf(var + 1e-5f);
    const float4 gg = reinterpret_cast<const float4*>(g)[t];
    const float4 bb = reinterpret_cast<const float4*>(b)[t];
    float4 o4;
    o4.x = (v.x - mean) * rstd * gg.x + bb.x;
    o4.y = (v.y - mean) * rstd * gg.y + bb.y;
    o4.z = (v.z - mean) * rstd * gg.z + bb.z;
    o4.w = (v.w - mean) * rstd * gg.w + bb.w;
    if (F32O) reinterpret_cast<float4*>(yf + (size_t)row * DMODEL)[t] = o4;
    if (SPL)  split_store4((char*)(yh + (size_t)row * DMODEL + t * 4),
                           (char*)(yl + (size_t)row * DMODEL + t * 4), o4);
}

// ===== flash attention 1 (rel, causal), 512 thr, warp-quads, cp.async ======
// grid (64, 16): blockIdx.x = b*8+n, blockIdx.y reversed i-tile (LPT order)
#define R_QH   0
#define R_QL   9216
#define R_KS0  18432     /* stage s: +s*18432; KH +0, KL +9216 */
#define R_VS0  55296
#define R_PH   92160
#define R_PL   101376
#define R_RH   110592
#define R_RL   129024
#define R_G    147456
#define R_C    181248    /* 2 x 64 floats */
#define R_PM   181760    /* 256 floats */
#define R_PS   182784    /* 256 floats */
#define REL_SMEM 183808

__global__ __launch_bounds__(512) void flash_rel_mma(
    const __nv_bfloat16* __restrict__ hh, const __nv_bfloat16* __restrict__ hl,
    const __nv_bfloat16* __restrict__ vth, const __nv_bfloat16* __restrict__ vtl,
    const __nv_bfloat16* __restrict__ rkh, const __nv_bfloat16* __restrict__ rkl,
    const float* __restrict__ cc,
    __nv_bfloat16* __restrict__ vech, __nv_bfloat16* __restrict__ vecl)
{
    extern __shared__ char sm[];
    const uint32_t sb = smem_u32(sm);
    const int tid = threadIdx.x, lane = tid & 31, wid = tid >> 5;
    const int p = wid >> 2, h = wid & 3;          // quad p (16 rows), quarter h
    const int i0 = (15 - (int)blockIdx.y) << 6;   // LPT: longest first
    const int b = blockIdx.x >> 3, n = blockIdx.x & 7;
    const int lr = lane & 7, lg = lane >> 3;
    const uint32_t a_off = (uint32_t)(((lg & 1) << 3) + lr) * 144u + (uint32_t)((lg >> 1) << 4);
    const uint32_t b_off = (uint32_t)(((lg >> 1) << 3) + lr) * 144u + (uint32_t)((lg & 1) << 4);
    const int qr_ = lane >> 2, qc_ = (lane & 3) << 1;
    float* G    = (float*)(sm + R_G);
    float* csm  = (float*)(sm + R_C);
    float* pmax = (float*)(sm + R_PM);
    float* psum = (float*)(sm + R_PS);
    const uint32_t AqH = sb + R_QH + p * 16 * 144, AqL = sb + R_QL + p * 16 * 144;
    const uint32_t ApH = sb + R_PH + p * 16 * 144, ApL = sb + R_PL + p * 16 * 144;
    const int ustart = 960 - i0;
    const int nit = (i0 >> 6) + 1;

    auto load_iter = [&](int k, int s) {
        const int j0k = k << 6;
        const uint32_t Ks = sb + R_KS0 + s * 18432;
        const uint32_t Vs = sb + R_VS0 + s * 18432;
        const int ub = ustart + ((k + 1) << 6);
        {
            const int row = tid >> 3, ch = tid & 7;   // 512 threads = full cover
            const size_t gk = ((size_t)(j0k + row) * 8 + b) * 1536 + 512 + n * 64 + ch * 8;
            cpa16(Ks + row * 144 + ch * 16, hh + gk);
            cpa16(Ks + 9216 + row * 144 + ch * 16, hl + gk);
            const size_t gv = ((size_t)(b * 8 + n) * 64 + row) * 1024 + j0k + ch * 8;
            cpa16(Vs + row * 144 + ch * 16, vth + gv);
            cpa16(Vs + 9216 + row * 144 + ch * 16, vtl + gv);
            const int u = ub + row;
            const int slot = u & 127;
            const int ok = (u < QLEN);
            const size_t gr = (size_t)(ok ? u : 0) * 512 + n * 64 + ch * 8;
            cpa16p(sb + R_RH + slot * 144 + ch * 16, rkh + gr, ok);
            cpa16p(sb + R_RL + slot * 144 + ch * 16, rkl + gr, ok);
        }
        if (tid < 64) csm[s * 64 + tid] = cc[n * 1152 + ub + tid];
        asm volatile("cp.async.commit_group;" ::: "memory");
    };

    // ---- prologue: Q tile, ring block0, c block0 (regular stores) ----
    {
        const int row = tid >> 3, c4 = tid & 7;
        const size_t g = ((size_t)(i0 + row) * 8 + b) * 1536 + n * 64 + c4 * 8;
        *(uint4*)(sm + R_QH + row * 144 + c4 * 16) = *(const uint4*)(hh + g);
        *(uint4*)(sm + R_QL + row * 144 + c4 * 16) = *(const uint4*)(hl + g);
    }
    {
        const int jr = tid >> 3, c4 = tid & 7;
        const int u = ustart + jr, slot = u & 127;
        uint4 vh = make_uint4(0, 0, 0, 0), vl = make_uint4(0, 0, 0, 0);
        if (u < QLEN) {
            const size_t g = (size_t)u * 512 + n * 64 + c4 * 8;
            vh = *(const uint4*)(rkh + g);
            vl = *(const uint4*)(rkl + g);
        }
        *(uint4*)(sm + R_RH + slot * 144 + c4 * 16) = vh;
        *(uint4*)(sm + R_RL + slot * 144 + c4 * 16) = vl;
    }
    if (tid < 64) csm[64 + tid] = cc[n * 1152 + ustart + tid];
    load_iter(0, 0);
    __syncthreads();

    // ---- G for block 0 ----
    {
        const int slotb = ustart & 127;
        float g2[2][4];
        #pragma unroll
        for (int nt = 0; nt < 2; nt++) { g2[nt][0]=0; g2[nt][1]=0; g2[nt][2]=0; g2[nt][3]=0; }
        wgemm3_nt2(AqH, AqL, sb + R_RH + (slotb + h * 16) * 144,
                   sb + R_RL + (slotb + h * 16) * 144, a_off, b_off, g2);
        #pragma unroll
        for (int nt = 0; nt < 2; nt++) {
            const int cl = h * 16 + (nt << 3) + qc_;
            const int col = slotb + cl;
            const float c0 = csm[64 + cl], c1 = csm[64 + cl + 1];
            *(float2*)&G[(16 * p + qr_) * 132 + col]     = make_float2(g2[nt][0] + c0, g2[nt][1] + c1);
            *(float2*)&G[(16 * p + qr_ + 8) * 132 + col] = make_float2(g2[nt][2] + c0, g2[nt][3] + c1);
        }
    }
    __syncthreads();

    float m0 = -1e30f, m1 = -1e30f, li0 = 0.f, li1 = 0.f;
    float o[2][4];
    #pragma unroll
    for (int nt = 0; nt < 2; nt++) { o[nt][0]=0; o[nt][1]=0; o[nt][2]=0; o[nt][3]=0; }

    for (int k = 0; k < nit; k++) {
        const int j0 = k << 6;
        if (k + 1 < nit) {
            load_iter(k + 1, (k + 1) & 1);
            asm volatile("cp.async.wait_group 1;" ::: "memory");
        } else {
            asm volatile("cp.async.wait_group 0;" ::: "memory");
        }
        __syncthreads();
        const uint32_t Ks = sb + R_KS0 + (k & 1) * 18432;
        const uint32_t Vs = sb + R_VS0 + (k & 1) * 18432;
        const float* csmb = csm + (k & 1) * 64;

        // G for block ustart + 64(k+1)
        {
            const int slotb = (ustart + ((k + 1) << 6)) & 127;
            float g2[2][4];
            #pragma unroll
            for (int nt = 0; nt < 2; nt++) { g2[nt][0]=0; g2[nt][1]=0; g2[nt][2]=0; g2[nt][3]=0; }
            wgemm3_nt2(AqH, AqL, sb + R_RH + (slotb + h * 16) * 144,
                       sb + R_RL + (slotb + h * 16) * 144, a_off, b_off, g2);
            #pragma unroll
            for (int nt = 0; nt < 2; nt++) {
                const int cl = h * 16 + (nt << 3) + qc_;
                const int col = slotb + cl;
                const float c0 = csmb[cl], c1 = csmb[cl + 1];
                *(float2*)&G[(16 * p + qr_) * 132 + col]     = make_float2(g2[nt][0] + c0, g2[nt][1] + c1);
                *(float2*)&G[(16 * p + qr_ + 8) * 132 + col] = make_float2(g2[nt][2] + c0, g2[nt][3] + c1);
            }
        }
        // QK: j-quarter h
        float s[2][4];
        #pragma unroll
        for (int nt = 0; nt < 2; nt++) { s[nt][0]=0; s[nt][1]=0; s[nt][2]=0; s[nt][3]=0; }
        wgemm3_nt2(AqH, AqL, Ks + h * 16 * 144, Ks + 9216 + h * 16 * 144,
                   a_off, b_off, s);
        barq(1 + p);   // quad's G writes visible before gather
        // gather BD + scale + mask
        const int cb = 1023 + j0 - i0;
        const int rA = 16 * p + qr_, rB = rA + 8;
        float rmax0 = -1e30f, rmax1 = -1e30f;
        #pragma unroll
        for (int nt = 0; nt < 2; nt++) {
            const int col = h * 16 + (nt << 3) + qc_;
            s[nt][0] = (s[nt][0] + G[rA * 132 + ((cb + col - rA) & 127)]) * ATT_SCALE;
            s[nt][1] = (s[nt][1] + G[rA * 132 + ((cb + col + 1 - rA) & 127)]) * ATT_SCALE;
            s[nt][2] = (s[nt][2] + G[rB * 132 + ((cb + col - rB) & 127)]) * ATT_SCALE;
            s[nt][3] = (s[nt][3] + G[rB * 132 + ((cb + col + 1 - rB) & 127)]) * ATT_SCALE;
            if (j0 == i0) {
                if (col > rA)     s[nt][0] = -1e30f;
                if (col + 1 > rA) s[nt][1] = -1e30f;
                if (col > rB)     s[nt][2] = -1e30f;
                if (col + 1 > rB) s[nt][3] = -1e30f;
            }
            rmax0 = fmaxf(rmax0, fmaxf(s[nt][0], s[nt][1]));
            rmax1 = fmaxf(rmax1, fmaxf(s[nt][2], s[nt][3]));
        }
        rmax0 = fmaxf(rmax0, __shfl_xor_sync(0xffffffffu, rmax0, 1));
        rmax0 = fmaxf(rmax0, __shfl_xor_sync(0xffffffffu, rmax0, 2));
        rmax1 = fmaxf(rmax1, __shfl_xor_sync(0xffffffffu, rmax1, 1));
        rmax1 = fmaxf(rmax1, __shfl_xor_sync(0xffffffffu, rmax1, 2));
        if ((lane & 3) == 0) {
            pmax[(p * 4 + h) * 16 + qr_]     = rmax0;
            pmax[(p * 4 + h) * 16 + qr_ + 8] = rmax1;
        }
        barq(1 + p);
        #pragma unroll
        for (int hh = 0; hh < 4; hh++) {
            rmax0 = fmaxf(rmax0, pmax[(p * 4 + hh) * 16 + qr_]);
            rmax1 = fmaxf(rmax1, pmax[(p * 4 + hh) * 16 + qr_ + 8]);
        }
        const float mn0 = fmaxf(m0, rmax0), mn1 = fmaxf(m1, rmax1);
        const float al0 = __expf(m0 - mn0), al1 = __expf(m1 - mn1);
        float rs0 = 0.f, rs1 = 0.f;
        #pragma unroll
        for (int nt = 0; nt < 2; nt++) {
            const int col = h * 16 + (nt << 3) + qc_;
            const float p0 = __expf(s[nt][0] - mn0), p1 = __expf(s[nt][1] - mn0);
            const float p2 = __expf(s[nt][2] - mn1), p3 = __expf(s[nt][3] - mn1);
            rs0 += p0 + p1; rs1 += p2 + p3;
            const __nv_bfloat16 h0 = __float2bfloat16(p0), h1 = __float2bfloat16(p1);
            const __nv_bfloat16 h2 = __float2bfloat16(p2), h3 = __float2bfloat16(p3);
            *(__nv_bfloat162*)(sm + R_PH + rA * 144 + col * 2) = __halves2bfloat162(h0, h1);
            *(__nv_bfloat162*)(sm + R_PL + rA * 144 + col * 2) = __halves2bfloat162(
                __float2bfloat16(p0 - __bfloat162float(h0)),
                __float2bfloat16(p1 - __bfloat162float(h1)));
            *(__nv_bfloat162*)(sm + R_PH + rB * 144 + col * 2) = __halves2bfloat162(h2, h3);
            *(__nv_bfloat162*)(sm + R_PL + rB * 144 + col * 2) = __halves2bfloat162(
                __float2bfloat16(p2 - __bfloat162float(h2)),
                __float2bfloat16(p3 - __bfloat162float(h3)));
            o[nt][0] *= al0; o[nt][1] *= al0; o[nt][2] *= al1; o[nt][3] *= al1;
        }
        rs0 += __shfl_xor_sync(0xffffffffu, rs0, 1);
        rs0 += __shfl_xor_sync(0xffffffffu, rs0, 2);
        rs1 += __shfl_xor_sync(0xffffffffu, rs1, 1);
        rs1 += __shfl_xor_sync(0xffffffffu, rs1, 2);
        if ((lane & 3) == 0) {
            psum[(p * 4 + h) * 16 + qr_]     = rs0;
            psum[(p * 4 + h) * 16 + qr_ + 8] = rs1;
        }
        barq(1 + p);   // psum exchange + P visibility within quad
        rs0 = 0.f; rs1 = 0.f;
        #pragma unroll
        for (int hh = 0; hh < 4; hh++) {
            rs0 += psum[(p * 4 + hh) * 16 + qr_];
            rs1 += psum[(p * 4 + hh) * 16 + qr_ + 8];
        }
        li0 = li0 * al0 + rs0; li1 = li1 * al1 + rs1;
        m0 = mn0; m1 = mn1;
        // PV: d-quarter h, K = full 64 j
        wgemm3_nt2(ApH, ApL, Vs + h * 16 * 144, Vs + 9216 + h * 16 * 144,
                   a_off, b_off, o);
        __syncthreads();
    }

    const float iv0 = 1.f / li0, iv1 = 1.f / li1;
    const int rA = 16 * p + qr_;
    #pragma unroll
    for (int nt = 0; nt < 2; nt++) {
        const int d = h * 16 + (nt << 3) + qc_;
        const float v0 = o[nt][0] * iv0, v1 = o[nt][1] * iv0;
        const float v2 = o[nt][2] * iv1, v3 = o[nt][3] * iv1;
        const size_t gA = ((size_t)(i0 + rA) * 8 + b) * 512 + n * 64 + d;
        const size_t gB = ((size_t)(i0 + rA + 8) * 8 + b) * 512 + n * 64 + d;
        const __nv_bfloat16 h0 = __float2bfloat16(v0), h1 = __float2bfloat16(v1);
        const __nv_bfloat16 h2 = __float2bfloat16(v2), h3 = __float2bfloat16(v3);
        *(__nv_bfloat162*)(vech + gA) = __halves2bfloat162(h0, h1);
        *(__nv_bfloat162*)(vecl + gA) = __halves2bfloat162(
            __float2bfloat16(v0 - __bfloat162float(h0)),
            __float2bfloat16(v1 - __bfloat162float(h1)));
        *(__nv_bfloat162*)(vech + gB) = __halves2bfloat162(h2, h3);
        *(__nv_bfloat162*)(vecl + gB) = __halves2bfloat162(
            __float2bfloat16(v2 - __bfloat162float(h2)),
            __float2bfloat16(v3 - __bfloat162float(h3)));
    }
}

// ===== flash attention 2 (cross), 256 thr, 64-row Q tile, 2 CTAs/SM =========
#define C_QH   0
#define C_QL   9216
#define C_KS0  18432     /* stage s: +s*18432; KH +0, KL +9216 */
#define C_VS0  55296
#define C_PH   92160
#define C_PL   101376
#define C_PM   110592    /* 512B */
#define C_PS   111104    /* 512B */
#define C_FL0  111616    /* 2 x 64 bytes */
#define CTX_SMEM 111744

__global__ __launch_bounds__(256, 2) void flash_ctx_mma(
    const __nv_bfloat16* __restrict__ qh, const __nv_bfloat16* __restrict__ ql,
    const __nv_bfloat16* __restrict__ kvh, const __nv_bfloat16* __restrict__ kvl,
    const __nv_bfloat16* __restrict__ vth, const __nv_bfloat16* __restrict__ vtl,
    const unsigned char* __restrict__ emask,
    __nv_bfloat16* __restrict__ vech, __nv_bfloat16* __restrict__ vecl)
{
    extern __shared__ char sm[];
    const uint32_t sb = smem_u32(sm);
    const int tid = threadIdx.x, lane = tid & 31, wid = tid >> 5;
    const int p = wid >> 1, h = wid & 1;
    const int i0 = blockIdx.x << 6;
    const int b = blockIdx.y >> 3, n = blockIdx.y & 7;
    const int lr = lane & 7, lg = lane >> 3;
    const uint32_t a_off = (uint32_t)(((lg & 1) << 3) + lr) * 144u + (uint32_t)((lg >> 1) << 4);
    const uint32_t b_off = (uint32_t)(((lg >> 1) << 3) + lr) * 144u + (uint32_t)((lg & 1) << 4);
    const int qr_ = lane >> 2, qc_ = (lane & 3) << 1;
    float* pmax = (float*)(sm + C_PM);
    float* psum = (float*)(sm + C_PS);
    const uint32_t AqH = sb + C_QH + p * 16 * 144, AqL = sb + C_QL + p * 16 * 144;
    const uint32_t ApH = sb + C_PH + p * 16 * 144, ApL = sb + C_PL + p * 16 * 144;
    const int nit = ELEN >> 6;

    auto load_iter = [&](int k, int s) {
        const int j0k = k << 6;
        const uint32_t Ks = sb + C_KS0 + s * 18432;
        const uint32_t Vs = sb + C_VS0 + s * 18432;
        #pragma unroll 2
        for (int i = tid; i < 512; i += 256) {
            const int row = i >> 3, ch = i & 7;
            const size_t gk = ((size_t)(j0k + row) * 8 + b) * 1024 + n * 64 + ch * 8;
            cpa16(Ks + row * 144 + ch * 16, kvh + gk);
            cpa16(Ks + 9216 + row * 144 + ch * 16, kvl + gk);
            const size_t gv = ((size_t)(b * 8 + n) * 64 + row) * 1024 + j0k + ch * 8;
            cpa16(Vs + row * 144 + ch * 16, vth + gv);
            cpa16(Vs + 9216 + row * 144 + ch * 16, vtl + gv);
        }
        if (tid < 64) sm[C_FL0 + s * 64 + tid] = (char)emask[(size_t)(j0k + tid) * 8 + b];
        asm volatile("cp.async.commit_group;" ::: "memory");
    };

    for (int t = tid; t < 512; t += 256) {
        const int row = t >> 3, c4 = t & 7;
        const size_t g = ((size_t)(i0 + row) * 8 + b) * 512 + n * 64 + c4 * 8;
        *(uint4*)(sm + C_QH + row * 144 + c4 * 16) = *(const uint4*)(qh + g);
        *(uint4*)(sm + C_QL + row * 144 + c4 * 16) = *(const uint4*)(ql + g);
    }
    load_iter(0, 0);

    float m0 = -1e30f, m1 = -1e30f, li0 = 0.f, li1 = 0.f;
    float o[4][4];
    #pragma unroll
    for (int nt = 0; nt < 4; nt++) { o[nt][0]=0; o[nt][1]=0; o[nt][2]=0; o[nt][3]=0; }

    for (int k = 0; k < nit; k++) {
        if (k + 1 < nit) {
            load_iter(k + 1, (k + 1) & 1);
            asm volatile("cp.async.wait_group 1;" ::: "memory");
        } else {
            asm volatile("cp.async.wait_group 0;" ::: "memory");
        }
        __syncthreads();
        const uint32_t Ks = sb + C_KS0 + (k & 1) * 18432;
        const uint32_t Vs = sb + C_VS0 + (k & 1) * 18432;
        const int fl = C_FL0 + (k & 1) * 64;

        // QK: this warp handles j-cols [h*32, h*32+32)
        float s[4][4];
        #pragma unroll
        for (int nt = 0; nt < 4; nt++) { s[nt][0]=0; s[nt][1]=0; s[nt][2]=0; s[nt][3]=0; }
        wgemm3_nt4(AqH, AqL, Ks + h * 32 * 144, Ks + 9216 + h * 32 * 144,
                   a_off, b_off, s);

        const int rA = 16 * p + qr_, rB = rA + 8;
        float rmax0 = -1e30f, rmax1 = -1e30f;
        #pragma unroll
        for (int nt = 0; nt < 4; nt++) {
            const int col = h * 32 + (nt << 3) + qc_;
            const bool f0 = sm[fl + col] != 0, f1 = sm[fl + col + 1] != 0;
            s[nt][0] = f0 ? -1e4f : s[nt][0] * ATT_SCALE;
            s[nt][1] = f1 ? -1e4f : s[nt][1] * ATT_SCALE;
            s[nt][2] = f0 ? -1e4f : s[nt][2] * ATT_SCALE;
            s[nt][3] = f1 ? -1e4f : s[nt][3] * ATT_SCALE;
            rmax0 = fmaxf(rmax0, fmaxf(s[nt][0], s[nt][1]));
            rmax1 = fmaxf(rmax1, fmaxf(s[nt][2], s[nt][3]));
        }
        rmax0 = fmaxf(rmax0, __shfl_xor_sync(0xffffffffu, rmax0, 1));
        rmax0 = fmaxf(rmax0, __shfl_xor_sync(0xffffffffu, rmax0, 2));
        rmax1 = fmaxf(rmax1, __shfl_xor_sync(0xffffffffu, rmax1, 1));
        rmax1 = fmaxf(rmax1, __shfl_xor_sync(0xffffffffu, rmax1, 2));
        if ((lane & 3) == 0) {
            pmax[p * 32 + h * 16 + qr_]     = rmax0;
            pmax[p * 32 + h * 16 + qr_ + 8] = rmax1;
        }
        barp(1 + p);
        rmax0 = fmaxf(rmax0, pmax[p * 32 + (1 - h) * 16 + qr_]);
        rmax1 = fmaxf(rmax1, pmax[p * 32 + (1 - h) * 16 + qr_ + 8]);
        const float mn0 = fmaxf(m0, rmax0), mn1 = fmaxf(m1, rmax1);
        const float al0 = __expf(m0 - mn0), al1 = __expf(m1 - mn1);
        float rs0 = 0.f, rs1 = 0.f;
        #pragma unroll
        for (int nt = 0; nt < 4; nt++) {
            const int col = h * 32 + (nt << 3) + qc_;
            const float p0 = __expf(s[nt][0] - mn0), p1 = __expf(s[nt][1] - mn0);
            const float p2 = __expf(s[nt][2] - mn1), p3 = __expf(s[nt][3] - mn1);
            rs0 += p0 + p1; rs1 += p2 + p3;
            const __nv_bfloat16 h0 = __float2bfloat16(p0), h1 = __float2bfloat16(p1);
            const __nv_bfloat16 h2 = __float2bfloat16(p2), h3 = __float2bfloat16(p3);
            *(__nv_bfloat162*)(sm + C_PH + rA * 144 + col * 2) = __halves2bfloat162(h0, h1);
            *(__nv_bfloat162*)(sm + C_PL + rA * 144 + col * 2) = __halves2bfloat162(
                __float2bfloat16(p0 - __bfloat162float(h0)),
                __float2bfloat16(p1 - __bfloat162float(h1)));
            *(__nv_bfloat162*)(sm + C_PH + rB * 144 + col * 2) = __halves2bfloat162(h2, h3);
            *(__nv_bfloat162*)(sm + C_PL + rB * 144 + col * 2) = __halves2bfloat162(
                __float2bfloat16(p2 - __bfloat162float(h2)),
                __float2bfloat16(p3 - __bfloat162float(h3)));
            o[nt][0] *= al0; o[nt][1] *= al0; o[nt][2] *= al1; o[nt][3] *= al1;
        }
        rs0 += __shfl_xor_sync(0xffffffffu, rs0, 1);
        rs0 += __shfl_xor_sync(0xffffffffu, rs0, 2);
        rs1 += __shfl_xor_sync(0xffffffffu, rs1, 1);
        rs1 += __shfl_xor_sync(0xffffffffu, rs1, 2);
        if ((lane & 3) == 0) {
            psum[p * 32 + h * 16 + qr_]     = rs0;
            psum[p * 32 + h * 16 + qr_ + 8] = rs1;
        }
        barp(1 + p);   // psum exchange + partner P visibility
        rs0 += psum[p * 32 + (1 - h) * 16 + qr_];
        rs1 += psum[p * 32 + (1 - h) * 16 + qr_ + 8];
        li0 = li0 * al0 + rs0; li1 = li1 * al1 + rs1;
        m0 = mn0; m1 = mn1;
        // PV: d-cols half h
        wgemm3_nt4(ApH, ApL, Vs + h * 32 * 144, Vs + 9216 + h * 32 * 144,
                   a_off, b_off, o);
        __syncthreads();
    }

    const float iv0 = 1.f / li0, iv1 = 1.f / li1;
    const int rA = 16 * p + qr_;
    #pragma unroll
    for (int nt = 0; nt < 4; nt++) {
        const int d = h * 32 + (nt << 3) + qc_;
        const float v0 = o[nt][0] * iv0, v1 = o[nt][1] * iv0;
        const float v2 = o[nt][2] * iv1, v3 = o[nt][3] * iv1;
        const size_t gA = ((size_t)(i0 + rA) * 8 + b) * 512 + n * 64 + d;
        const size_t gB = ((size_t)(i0 + rA + 8) * 8 + b) * 512 + n * 64 + d;
        const __nv_bfloat16 h0 = __float2bfloat16(v0), h1 = __float2bfloat16(v1);
        const __nv_bfloat16 h2 = __float2bfloat16(v2), h3 = __float2bfloat16(v3);
        *(__nv_bfloat162*)(vech + gA) = __halves2bfloat162(h0, h1);
        *(__nv_bfloat162*)(vecl + gA) = __halves2bfloat162(
            __float2bfloat16(v0 - __bfloat162float(h0)),
            __float2bfloat16(v1 - __bfloat162float(h1)));
        *(__nv_bfloat162*)(vech + gB) = __halves2bfloat162(h2, h3);
        *(__nv_bfloat162*)(vecl + gB) = __halves2bfloat162(
            __float2bfloat16(v2 - __bfloat162float(h2)),
            __float2bfloat16(v3 - __bfloat162float(h3)));
    }
}

// ===================== host orchestration ====================================
extern "C" void kernel_launch(void* const* d_in, const int* in_sizes, int n_in,
                              void* d_out, int out_size)
{
    (void)in_sizes; (void)n_in; (void)out_size;
    const float* dec_inp = (const float*)d_in[0];
    const float* r       = (const float*)d_in[1];
    const float* enc_out = (const float*)d_in[2];
    const float* rwb     = (const float*)d_in[3];
    const float* rrb     = (const float*)d_in[4];
    const float* qkv_w   = (const float*)d_in[5];
    const float* r_w     = (const float*)d_in[6];
    const float* o_w     = (const float*)d_in[7];
    const float* ln1_g   = (const float*)d_in[8];
    const float* ln1_b   = (const float*)d_in[9];
    const float* q_w     = (const float*)d_in[10];
    const float* kv_w    = (const float*)d_in[11];
    const float* o2_w    = (const float*)d_in[12];
    const float* ln2_g   = (const float*)d_in[13];
    const float* ln2_b   = (const float*)d_in[14];
    const float* ff_w1   = (const float*)d_in[15];
    const float* ff_b1   = (const float*)d_in[16];
    const float* ff_w2   = (const float*)d_in[17];
    const float* ff_b2   = (const float*)d_in[18];
    const float* ln3_g   = (const float*)d_in[19];
    const float* ln3_b   = (const float*)d_in[20];
    const unsigned char* emask = (const unsigned char*)d_in[22];
    float* out = (float*)d_out;

    float *out1, *h2, *out2, *qbias, *ccv;
    __nv_bfloat16 *wthi, *wtlo, *hh, *hl, *headsh, *headsl, *rh, *rl, *rkh, *rkl;
    __nv_bfloat16 *vth, *vtl, *vech, *vecl, *h2h, *h2l, *q2h, *q2l, *eh, *el;
    __nv_bfloat16 *kvh, *kvl, *vt2h, *vt2l, *vec2h, *vec2l, *th, *tl;
    cudaGetSymbolAddress((void**)&out1,  g_out1);
    cudaGetSymbolAddress((void**)&h2,    g_h2);
    cudaGetSymbolAddress((void**)&out2,  g_out2);
    cudaGetSymbolAddress((void**)&qbias, g_qbias);
    cudaGetSymbolAddress((void**)&ccv,   g_cc);
    cudaGetSymbolAddress((void**)&wthi,  g_wthi);
    cudaGetSymbolAddress((void**)&wtlo,  g_wtlo);
    cudaGetSymbolAddress((void**)&hh,    g_hh);
    cudaGetSymbolAddress((void**)&hl,    g_hl);
    cudaGetSymbolAddress((void**)&headsh,g_headsh);
    cudaGetSymbolAddress((void**)&headsl,g_headsl);
    cudaGetSymbolAddress((void**)&rh,    g_rh);
    cudaGetSymbolAddress((void**)&rl,    g_rl);
    cudaGetSymbolAddress((void**)&rkh,   g_rkh);
    cudaGetSymbolAddress((void**)&rkl,   g_rkl);
    cudaGetSymbolAddress((void**)&vth,   g_vth);
    cudaGetSymbolAddress((void**)&vtl,   g_vtl);
    cudaGetSymbolAddress((void**)&vech,  g_vech);
    cudaGetSymbolAddress((void**)&vecl,  g_vecl);
    cudaGetSymbolAddress((void**)&h2h,   g_h2h);
    cudaGetSymbolAddress((void**)&h2l,   g_h2l);
    cudaGetSymbolAddress((void**)&q2h,   g_q2h);
    cudaGetSymbolAddress((void**)&q2l,   g_q2l);
    cudaGetSymbolAddress((void**)&eh,    g_eh);
    cudaGetSymbolAddress((void**)&el,    g_el);
    cudaGetSymbolAddress((void**)&kvh,   g_kvh);
    cudaGetSymbolAddress((void**)&kvl,   g_kvl);
    cudaGetSymbolAddress((void**)&vt2h,  g_vt2h);
    cudaGetSymbolAddress((void**)&vt2l,  g_vt2l);
    cudaGetSymbolAddress((void**)&vec2h, g_vec2h);
    cudaGetSymbolAddress((void**)&vec2l, g_vec2l);
    cudaGetSymbolAddress((void**)&th,    g_th);
    cudaGetSymbolAddress((void**)&tl,    g_tl);

    cudaFuncSetAttribute(flash_rel_mma, cudaFuncAttributeMaxDynamicSharedMemorySize, REL_SMEM);
    cudaFuncSetAttribute(flash_ctx_mma, cudaFuncAttributeMaxDynamicSharedMemorySize, CTX_SMEM);
    cudaFuncSetAttribute(gemm_hmma<false, false>, cudaFuncAttributeMaxDynamicSharedMemorySize, GP_SMEM);
    cudaFuncSetAttribute(gemm_hmma<false, true>,  cudaFuncAttributeMaxDynamicSharedMemorySize, GP_SMEM);
    cudaFuncSetAttribute(gemm_hmma<true, true>,   cudaFuncAttributeMaxDynamicSharedMemorySize, GP_SMEM);

    // ---- two-stream fork/join (graph-capture-legal pattern) ----
    cudaStream_t s1;
    cudaStreamCreateWithFlags(&s1, cudaStreamNonBlocking);
    cudaEvent_t e0, eP, eW, eC, eKV;
    cudaEventCreateWithFlags(&e0,  cudaEventDisableTiming);
    cudaEventCreateWithFlags(&eP,  cudaEventDisableTiming);
    cudaEventCreateWithFlags(&eW,  cudaEventDisableTiming);
    cudaEventCreateWithFlags(&eC,  cudaEventDisableTiming);
    cudaEventCreateWithFlags(&eKV, cudaEventDisableTiming);

    cudaEventRecord(e0, 0);
    cudaStreamWaitEvent(s1, e0, 0);

    // stream 0: weight prep
    tsplit_all<<<4352, 256>>>(qkv_w, r_w, o_w, q_w, kv_w, o2_w, ff_w1, ff_w2,
                              wthi, wtlo);
    qbias_k<<<6, 256>>>(rwb, qbias);
    cudaEventRecord(eW, 0);

    // stream 1: activation prep
    ln_k<false, true><<<ROWS, 128, 0, s1>>>(dec_inp, ln1_g, ln1_b, nullptr, hh, hl);
    split_k<<<QLEN * DMODEL / 1024, 256, 0, s1>>>(r, rh, rl, QLEN * DMODEL / 4);
    split_k<<<ROWS * DMODEL / 1024, 256, 0, s1>>>(enc_out, eh, el, ROWS * DMODEL / 4);
    cudaEventRecord(eP, s1);

    // stream 0 spine: qkv -> vtrans1
    cudaStreamWaitEvent(0, eP, 0);
    gemm_hmma<false, true><<<dim3(12, 64), 256, GP_SMEM>>>(
        hh, hl, wthi + WT_QKV, wtlo + WT_QKV, qbias, nullptr,
        nullptr, headsh, headsl, ROWS, 1536, 512);
    vtrans_k<<<dim3(32, 64), 256>>>(headsh, headsl, vth, vtl, 1536, 1024);

    // stream 1 branch: rk -> c_k, then kv -> vtrans2 (overlaps flash_rel)
    cudaStreamWaitEvent(s1, eW, 0);
    gemm_hmma<false, true><<<dim3(4, 8), 256, GP_SMEM, s1>>>(
        rh, rl, wthi + WT_RW, wtlo + WT_RW, nullptr, nullptr,
        nullptr, rkh, rkl, QLEN, 512, 512);
    c_k<<<1024, 256, 0, s1>>>(rkh, rkl, rwb, rrb, ccv);
    cudaEventRecord(eC, s1);
    gemm_hmma<false, true><<<dim3(8, 64), 256, GP_SMEM, s1>>>(
        eh, el, wthi + WT_KVW, wtlo + WT_KVW, nullptr, nullptr,
        nullptr, kvh, kvl, ROWS, 1024, 512);
    vtrans_k<<<dim3(32, 64), 256, 0, s1>>>(kvh, kvl, vt2h, vt2l, 1024, 512);
    cudaEventRecord(eKV, s1);

    // stream 0: block 1 tail + block 2 head
    cudaStreamWaitEvent(0, eC, 0);
    flash_rel_mma<<<dim3(64, 16), 512, REL_SMEM>>>(headsh, headsl, vth, vtl,
                                                   rkh, rkl, ccv, vech, vecl);
    gemm_hmma<false, false><<<dim3(4, 64), 256, GP_SMEM>>>(
        vech, vecl, wthi + WT_OW, wtlo + WT_OW, nullptr, dec_inp,
        out1, nullptr, nullptr, ROWS, 512, 512);
    ln_k<true, true><<<ROWS, 128>>>(out1, ln2_g, ln2_b, h2, h2h, h2l);
    gemm_hmma<false, true><<<dim3(4, 64), 256, GP_SMEM>>>(
        h2h, h2l, wthi + WT_QW, wtlo + WT_QW, nullptr, nullptr,
        nullptr, q2h, q2l, ROWS, 512, 512);

    // join: cross attention needs kv/vt2 from stream 1
    cudaStreamWaitEvent(0, eKV, 0);
    flash_ctx_mma<<<dim3(16, 64), 256, CTX_SMEM>>>(q2h, q2l, kvh, kvl, vt2h, vt2l,
                                                   emask, vec2h, vec2l);
    gemm_hmma<false, false><<<dim3(4, 64), 256, GP_SMEM>>>(
        vec2h, vec2l, wthi + WT_O2W, wtlo + WT_O2W, nullptr, h2,
        out2, nullptr, nullptr, ROWS, 512, 512);

    // ---- block 3: FF ----
    ln_k<false, true><<<ROWS, 128>>>(out2, ln3_g, ln3_b, nullptr, hh, hl);
    gemm_hmma<true, true><<<dim3(16, 64), 256, GP_SMEM>>>(
        hh, hl, wthi + WT_FF1, wtlo + WT_FF1, ff_b1, nullptr,
        nullptr, th, tl, ROWS, 2048, 512);
    gemm_hmma<false, false><<<dim3(4, 64), 256, GP_SMEM>>>(
        th, tl, wthi + WT_FF2, wtlo + WT_FF2, ff_b2, out2,
        out, nullptr, nullptr, ROWS, 512, 2048);

    // destroy only when NOT capturing (destroying mid-capture invalidates the graph)
    cudaStreamCaptureStatus st = cudaStreamCaptureStatusNone;
    cudaStreamIsCapturing(0, &st);
    if (st == cudaStreamCaptureStatusNone) {
        cudaStreamDestroy(s1);
        cudaEventDestroy(e0);
        cudaEventDestroy(eP);
        cudaEventDestroy(eW);
        cudaEventDestroy(eC);
        cudaEventDestroy(eKV);
    }
}